// round 2
// baseline (speedup 1.0000x reference)
#include <cuda_runtime.h>
#include <math.h>

#define TT 4096
#define DD 256
#define HH 1024
#define EE 8

// ---------------- device-global scratch (allocation-free) ----------------
__device__ int   g_count[EE];
__device__ int   g_tok[EE * TT];
__device__ int   g_pos[TT * 2];
__device__ float g_gv[TT * 2];
__device__ float g_h1[(size_t)EE * TT * HH];
__device__ float g_o2[(size_t)EE * TT * DD];

// ---------------- helpers ----------------
__device__ __forceinline__ unsigned f2tf(float f) {
    unsigned r;
    asm("cvt.rna.tf32.f32 %0, %1;" : "=r"(r) : "f"(f));
    return r;
}

__device__ __forceinline__ void mma8(float* c, const unsigned* a, const unsigned* b) {
    asm volatile(
        "mma.sync.aligned.m16n8k8.row.col.f32.tf32.tf32.f32 "
        "{%0,%1,%2,%3}, {%4,%5,%6,%7}, {%8,%9}, {%0,%1,%2,%3};\n"
        : "+f"(c[0]), "+f"(c[1]), "+f"(c[2]), "+f"(c[3])
        : "r"(a[0]), "r"(a[1]), "r"(a[2]), "r"(a[3]), "r"(b[0]), "r"(b[1]));
}

// ---------------- kernel 0: zero counters ----------------
__global__ void zero_counts_kernel() {
    if (threadIdx.x < EE) g_count[threadIdx.x] = 0;
}

// ---------------- kernel 1: gating (one warp per token) ----------------
__global__ void gate_kernel(const float* __restrict__ x, const float* __restrict__ wg) {
    __shared__ float swg[DD * EE];
    const int tid = threadIdx.x;
    for (int i = tid; i < DD * EE; i += 128) swg[i] = wg[i];
    __syncthreads();
    const int lane = tid & 31, warp = tid >> 5;
    const int t = blockIdx.x * 4 + warp;

    float xr[8];
#pragma unroll
    for (int j = 0; j < 8; j++) xr[j] = x[(size_t)t * DD + lane + 32 * j];

    float logit[EE];
#pragma unroll
    for (int e = 0; e < EE; e++) {
        float p = 0.f;
#pragma unroll
        for (int j = 0; j < 8; j++) p += xr[j] * swg[(lane + 32 * j) * EE + e];
#pragma unroll
        for (int off = 16; off > 0; off >>= 1) p += __shfl_xor_sync(0xffffffffu, p, off);
        logit[e] = p;
    }

    if (lane == 0) {
        int i0 = 0; float v0 = logit[0];
#pragma unroll
        for (int e = 1; e < EE; e++) if (logit[e] > v0) { v0 = logit[e]; i0 = e; }
        int i1 = -1; float v1 = -INFINITY;
#pragma unroll
        for (int e = 0; e < EE; e++) if (e != i0 && logit[e] > v1) { v1 = logit[e]; i1 = e; }

        const float e1  = expf(v1 - v0);
        const float inv = 1.f / (1.f + e1);
        const float g0 = inv, g1 = e1 * inv;

        int p0 = atomicAdd(&g_count[i0], 1);
        g_tok[i0 * TT + p0] = t;
        g_pos[t * 2 + 0]    = i0 * TT + p0;
        g_gv[t * 2 + 0]     = g0;

        int p1 = atomicAdd(&g_count[i1], 1);
        g_tok[i1 * TT + p1] = t;
        g_pos[t * 2 + 1]    = i1 * TT + p1;
        g_gv[t * 2 + 1]     = g1;
    }
}

// ---------------- grouped TF32 GEMM with fragment-packed smem ----------------
// Tile: 64 x TN, BK=16. Warp tile 32x32 (2x4 m16n8k8 frags).
// A smem:  uint4 fragments, slot = (tg<<3)|(g^(tg<<1)), comp = 2*half8+khalf,
//          j-stride 144 words  -> conflict-free STS.32 stores and LDS.128 loads.
// B smem:  (k,k+4) uint2 pairs, col-stride 2*(TN+4) == 8 mod 32
//          -> conflict-free STS.128 stores and LDS.64 loads.
template <int ND, int KD, int TN, int NT, bool GATHER, bool RELU>
__global__ void __launch_bounds__(NT) moe_gemm_kernel(
    const float* __restrict__ Abase, const float* __restrict__ Bbase,
    const float* __restrict__ bias)
{
    constexpr int BK = 16, NK = KD / BK;
    constexpr int WN = TN / 32;
    constexpr int NCP = TN + 4;
    constexpr int SASTG = 2 * 4 * 144;       // words per A stage
    constexpr int SBSTG = 2 * 4 * NCP * 2;   // words per B stage
    constexpr int APER = 256 / NT;           // float4 A-tasks per thread
    constexpr int BPER = (TN * 4) / NT;      // B tasks per thread

    __shared__ __align__(16) unsigned SA[2 * SASTG];
    __shared__ __align__(16) unsigned SB[2 * SBSTG];

    const int e = blockIdx.z;
    const int M = g_count[e];
    const int row0 = blockIdx.y * 64;
    if (row0 >= M) return;
    const int col0 = blockIdx.x * TN;

    const int tid = threadIdx.x;
    const int lane = tid & 31, warp = tid >> 5;
    const int wm = warp / WN, wn = warp % WN;
    const int grp = lane >> 2, tg = lane & 3;

    // ---- producer task setup: A (64 x 16 floats = 256 float4 tasks) ----
    const float* Arow[APER];
    int aoff[APER], sabase[APER], aslot[APER][4];
    bool aval[APER];
#pragma unroll
    for (int ap = 0; ap < APER; ap++) {
        const int q = tid + ap * NT;
        const int ar = q & 63, khalf = (q >> 6) & 1, k8b = (q >> 7) & 1;
        const int g = ar & 7, h8 = (ar >> 3) & 1, j = ar >> 4;
        aval[ap] = (row0 + ar) < M;
        if (GATHER) {
            const int tok = aval[ap] ? g_tok[e * TT + row0 + ar] : 0;
            Arow[ap] = Abase + (size_t)tok * KD;
        } else {
            Arow[ap] = g_h1 + ((size_t)e * TT + row0 + ar) * KD;
        }
        aoff[ap]   = k8b * 8 + khalf * 4;
        sabase[ap] = (k8b * 4 + j) * 144 + 2 * h8 + khalf;
#pragma unroll
        for (int i = 0; i < 4; i++)
            aslot[ap][i] = ((i << 3) | (g ^ (i << 1))) * 4;
    }

    // ---- producer task setup: B ----
    const float* Bexp = Bbase + (size_t)e * KD * ND;
    const float* Bp0[BPER];
    int sbbase[BPER];
#pragma unroll
    for (int bp = 0; bp < BPER; bp++) {
        const int q = tid + bp * NT;
        const int cp = q & (TN / 2 - 1);
        const int rest = q / (TN / 2);
        const int p = rest & 3, k8 = (rest >> 2) & 1;
        Bp0[bp] = Bexp + (size_t)(k8 * 8 + p) * ND + col0 + 2 * cp;
        sbbase[bp] = (k8 * 4 + p) * (NCP * 2) + 4 * cp;
    }

    float acc[2][4][4];
#pragma unroll
    for (int i = 0; i < 2; i++)
#pragma unroll
        for (int j = 0; j < 4; j++)
#pragma unroll
            for (int q = 0; q < 4; q++) acc[i][j][q] = 0.f;

    float4 aR[APER];
    float2 bR[BPER][2];

    const int saoff = ((tg << 3) | (grp ^ (tg << 1))) * 4;

    auto load_g = [&](int ko) {
#pragma unroll
        for (int ap = 0; ap < APER; ap++)
            aR[ap] = aval[ap] ? *(const float4*)(Arow[ap] + ko + aoff[ap])
                              : make_float4(0.f, 0.f, 0.f, 0.f);
#pragma unroll
        for (int bp = 0; bp < BPER; bp++) {
            bR[bp][0] = *(const float2*)(Bp0[bp] + (size_t)ko * ND);
            bR[bp][1] = *(const float2*)(Bp0[bp] + (size_t)(ko + 4) * ND);
        }
    };

    auto store_s = [&](int st) {
#pragma unroll
        for (int ap = 0; ap < APER; ap++) {
            unsigned* base = SA + st * SASTG + sabase[ap];
            const float v[4] = {aR[ap].x, aR[ap].y, aR[ap].z, aR[ap].w};
#pragma unroll
            for (int i = 0; i < 4; i++)
                base[aslot[ap][i]] = f2tf(v[i]);
        }
#pragma unroll
        for (int bp = 0; bp < BPER; bp++) {
            uint4 u = { f2tf(bR[bp][0].x), f2tf(bR[bp][1].x),
                        f2tf(bR[bp][0].y), f2tf(bR[bp][1].y) };
            *(uint4*)(SB + st * SBSTG + sbbase[bp]) = u;
        }
    };

    auto compute = [&](int st) {
#pragma unroll
        for (int k8 = 0; k8 < 2; k8++) {
            const unsigned* pa = SA + st * SASTG + k8 * (4 * 144);
            const unsigned* pb = SB + st * SBSTG + k8 * (4 * NCP * 2);
            uint4 ua[2];
#pragma unroll
            for (int mt = 0; mt < 2; mt++)
                ua[mt] = *(const uint4*)(pa + (wm * 2 + mt) * 144 + saoff);
            uint2 ub[4];
#pragma unroll
            for (int nt = 0; nt < 4; nt++)
                ub[nt] = *(const uint2*)(pb + tg * (NCP * 2) +
                                         (wn * 32 + nt * 8 + grp) * 2);
#pragma unroll
            for (int mt = 0; mt < 2; mt++) {
                const unsigned a4[4] = {ua[mt].x, ua[mt].z, ua[mt].y, ua[mt].w};
#pragma unroll
                for (int nt = 0; nt < 4; nt++) {
                    const unsigned b2[2] = {ub[nt].x, ub[nt].y};
                    mma8(acc[mt][nt], a4, b2);
                }
            }
        }
    };

    load_g(0);
    store_s(0);
    __syncthreads();

#pragma unroll 1
    for (int kt = 0; kt < NK; kt++) {
        if (kt + 1 < NK) load_g((kt + 1) * BK);
        compute(kt & 1);
        if (kt + 1 < NK) {
            store_s((kt + 1) & 1);
            __syncthreads();
        }
    }

    // epilogue: bias (+ReLU), guarded float2 stores
    const float* bv = bias + e * ND;
    float* Cb = RELU ? g_h1 : g_o2;
#pragma unroll
    for (int mt = 0; mt < 2; mt++) {
        const int lr = wm * 32 + mt * 16 + grp;
#pragma unroll
        for (int half = 0; half < 2; half++) {
            const int r = row0 + lr + half * 8;
            if (r < M) {
                float* crow = Cb + ((size_t)e * TT + r) * ND;
#pragma unroll
                for (int nt = 0; nt < 4; nt++) {
                    const int c = col0 + wn * 32 + nt * 8 + 2 * tg;
                    float v0 = acc[mt][nt][half * 2 + 0] + bv[c];
                    float v1 = acc[mt][nt][half * 2 + 1] + bv[c + 1];
                    if (RELU) { v0 = fmaxf(v0, 0.f); v1 = fmaxf(v1, 0.f); }
                    *(float2*)(crow + c) = make_float2(v0, v1);
                }
            }
        }
    }
}

// ---------------- kernel 4: gated combine (deterministic) ----------------
__global__ void combine_kernel(float* __restrict__ y) {
    const int t  = blockIdx.x;
    const int d4 = threadIdx.x;
    const int   p0 = g_pos[t * 2],     p1 = g_pos[t * 2 + 1];
    const float g0 = g_gv[t * 2],      g1 = g_gv[t * 2 + 1];
    const float4 a = *(const float4*)(g_o2 + (size_t)p0 * DD + d4 * 4);
    const float4 b = *(const float4*)(g_o2 + (size_t)p1 * DD + d4 * 4);
    float4 r;
    r.x = g0 * a.x + g1 * b.x;
    r.y = g0 * a.y + g1 * b.y;
    r.z = g0 * a.z + g1 * b.z;
    r.w = g0 * a.w + g1 * b.w;
    *(float4*)(y + (size_t)t * DD + d4 * 4) = r;
}

// ---------------- launch ----------------
extern "C" void kernel_launch(void* const* d_in, const int* in_sizes, int n_in,
                              void* d_out, int out_size) {
    const float* x  = (const float*)d_in[0];
    const float* wg = (const float*)d_in[1];
    const float* W1 = (const float*)d_in[2];
    const float* b1 = (const float*)d_in[3];
    const float* W2 = (const float*)d_in[4];
    const float* b2 = (const float*)d_in[5];
    float* y = (float*)d_out;

    zero_counts_kernel<<<1, 32>>>();
    gate_kernel<<<TT / 4, 128>>>(x, wg);
    // GEMM1: (gathered tokens) x W1 -> relu(.+b1) into g_h1.  64x128 tiles.
    moe_gemm_kernel<HH, DD, 128, 256, true,  true ><<<dim3(HH / 128, TT / 64, EE), 256>>>(x, W1, b1);
    // GEMM2: g_h1 x W2 -> (.+b2) into g_o2.  64x64 tiles for SM coverage.
    moe_gemm_kernel<DD, HH, 64, 128, false, false><<<dim3(DD / 64, TT / 64, EE), 128>>>(nullptr, W2, b2);
    combine_kernel<<<TT, 64>>>(y);
}

// round 3
// speedup vs baseline: 1.0007x; 1.0007x over previous
#include <cuda_runtime.h>
#include <math.h>

#define TT 4096
#define DD 256
#define HH 1024
#define EE 8

// ---------------- device-global scratch (allocation-free) ----------------
__device__ int   g_count[EE];
__device__ int   g_tok[EE * TT];
__device__ int   g_pos[TT * 2];
__device__ float g_gv[TT * 2];
__device__ float g_h1[(size_t)EE * TT * HH];
__device__ float g_o2[(size_t)EE * TT * DD];

// ---------------- helpers ----------------
__device__ __forceinline__ unsigned f2tf(float f) {
    unsigned r;
    asm("cvt.rna.tf32.f32 %0, %1;" : "=r"(r) : "f"(f));
    return r;
}

__device__ __forceinline__ void mma8(float* c, const unsigned* a, const unsigned* b) {
    asm volatile(
        "mma.sync.aligned.m16n8k8.row.col.f32.tf32.tf32.f32 "
        "{%0,%1,%2,%3}, {%4,%5,%6,%7}, {%8,%9}, {%0,%1,%2,%3};\n"
        : "+f"(c[0]), "+f"(c[1]), "+f"(c[2]), "+f"(c[3])
        : "r"(a[0]), "r"(a[1]), "r"(a[2]), "r"(a[3]), "r"(b[0]), "r"(b[1]));
}

// ---------------- kernel 0: zero counters ----------------
__global__ void zero_counts_kernel() {
    if (threadIdx.x < EE) g_count[threadIdx.x] = 0;
}

// ---------------- kernel 1: gating (one warp per token) ----------------
__global__ void gate_kernel(const float* __restrict__ x, const float* __restrict__ wg) {
    __shared__ float swg[DD * EE];
    const int tid = threadIdx.x;
    for (int i = tid; i < DD * EE; i += 128) swg[i] = wg[i];
    __syncthreads();
    const int lane = tid & 31, warp = tid >> 5;
    const int t = blockIdx.x * 4 + warp;

    float xr[8];
#pragma unroll
    for (int j = 0; j < 8; j++) xr[j] = x[(size_t)t * DD + lane + 32 * j];

    float logit[EE];
#pragma unroll
    for (int e = 0; e < EE; e++) {
        float p = 0.f;
#pragma unroll
        for (int j = 0; j < 8; j++) p += xr[j] * swg[(lane + 32 * j) * EE + e];
#pragma unroll
        for (int off = 16; off > 0; off >>= 1) p += __shfl_xor_sync(0xffffffffu, p, off);
        logit[e] = p;
    }

    if (lane == 0) {
        int i0 = 0; float v0 = logit[0];
#pragma unroll
        for (int e = 1; e < EE; e++) if (logit[e] > v0) { v0 = logit[e]; i0 = e; }
        int i1 = -1; float v1 = -INFINITY;
#pragma unroll
        for (int e = 0; e < EE; e++) if (e != i0 && logit[e] > v1) { v1 = logit[e]; i1 = e; }

        const float e1  = expf(v1 - v0);
        const float inv = 1.f / (1.f + e1);
        const float g0 = inv, g1 = e1 * inv;

        int p0 = atomicAdd(&g_count[i0], 1);
        g_tok[i0 * TT + p0] = t;
        g_pos[t * 2 + 0]    = i0 * TT + p0;
        g_gv[t * 2 + 0]     = g0;

        int p1 = atomicAdd(&g_count[i1], 1);
        g_tok[i1 * TT + p1] = t;
        g_pos[t * 2 + 1]    = i1 * TT + p1;
        g_gv[t * 2 + 1]     = g1;
    }
}

// ---------------- grouped TF32 GEMM with fragment-packed smem ----------------
// Tile: 64 x TN, BK=16. Warp tile 32x32 (2x4 m16n8k8 frags).
// A smem:  uint4 fragments, slot = (tg<<3)|(g^(tg<<1)), comp = 2*half8+khalf,
//          j-stride 144 words  -> conflict-free STS.32 stores and LDS.128 loads.
// B smem:  (k,k+4) uint2 pairs, col-stride 2*(TN+4) == 8 mod 32
//          -> conflict-free STS.128 stores and LDS.64 loads.
template <int ND, int KD, int TN, int NT, bool GATHER, bool RELU>
__global__ void __launch_bounds__(NT) moe_gemm_kernel(
    const float* __restrict__ Abase, const float* __restrict__ Bbase,
    const float* __restrict__ bias)
{
    constexpr int BK = 16, NK = KD / BK;
    constexpr int WN = TN / 32;
    constexpr int NCP = TN + 4;
    constexpr int SASTG = 2 * 4 * 144;       // words per A stage
    constexpr int SBSTG = 2 * 4 * NCP * 2;   // words per B stage
    constexpr int APER = 256 / NT;           // float4 A-tasks per thread
    constexpr int BPER = (TN * 4) / NT;      // B tasks per thread

    __shared__ __align__(16) unsigned SA[2 * SASTG];
    __shared__ __align__(16) unsigned SB[2 * SBSTG];

    const int e = blockIdx.z;
    const int M = g_count[e];
    const int row0 = blockIdx.y * 64;
    if (row0 >= M) return;
    const int col0 = blockIdx.x * TN;

    const int tid = threadIdx.x;
    const int lane = tid & 31, warp = tid >> 5;
    const int wm = warp / WN, wn = warp % WN;
    const int grp = lane >> 2, tg = lane & 3;

    // ---- producer task setup: A (64 x 16 floats = 256 float4 tasks) ----
    const float* Arow[APER];
    int aoff[APER], sabase[APER], aslot[APER][4];
    bool aval[APER];
#pragma unroll
    for (int ap = 0; ap < APER; ap++) {
        const int q = tid + ap * NT;
        const int ar = q & 63, khalf = (q >> 6) & 1, k8b = (q >> 7) & 1;
        const int g = ar & 7, h8 = (ar >> 3) & 1, j = ar >> 4;
        aval[ap] = (row0 + ar) < M;
        if (GATHER) {
            const int tok = aval[ap] ? g_tok[e * TT + row0 + ar] : 0;
            Arow[ap] = Abase + (size_t)tok * KD;
        } else {
            Arow[ap] = g_h1 + ((size_t)e * TT + row0 + ar) * KD;
        }
        aoff[ap]   = k8b * 8 + khalf * 4;
        sabase[ap] = (k8b * 4 + j) * 144 + 2 * h8 + khalf;
#pragma unroll
        for (int i = 0; i < 4; i++)
            aslot[ap][i] = ((i << 3) | (g ^ (i << 1))) * 4;
    }

    // ---- producer task setup: B ----
    const float* Bexp = Bbase + (size_t)e * KD * ND;
    const float* Bp0[BPER];
    int sbbase[BPER];
#pragma unroll
    for (int bp = 0; bp < BPER; bp++) {
        const int q = tid + bp * NT;
        const int cp = q & (TN / 2 - 1);
        const int rest = q / (TN / 2);
        const int p = rest & 3, k8 = (rest >> 2) & 1;
        Bp0[bp] = Bexp + (size_t)(k8 * 8 + p) * ND + col0 + 2 * cp;
        sbbase[bp] = (k8 * 4 + p) * (NCP * 2) + 4 * cp;
    }

    float acc[2][4][4];
#pragma unroll
    for (int i = 0; i < 2; i++)
#pragma unroll
        for (int j = 0; j < 4; j++)
#pragma unroll
            for (int q = 0; q < 4; q++) acc[i][j][q] = 0.f;

    float4 aR[APER];
    float2 bR[BPER][2];

    const int saoff = ((tg << 3) | (grp ^ (tg << 1))) * 4;

    auto load_g = [&](int ko) {
#pragma unroll
        for (int ap = 0; ap < APER; ap++)
            aR[ap] = aval[ap] ? *(const float4*)(Arow[ap] + ko + aoff[ap])
                              : make_float4(0.f, 0.f, 0.f, 0.f);
#pragma unroll
        for (int bp = 0; bp < BPER; bp++) {
            bR[bp][0] = *(const float2*)(Bp0[bp] + (size_t)ko * ND);
            bR[bp][1] = *(const float2*)(Bp0[bp] + (size_t)(ko + 4) * ND);
        }
    };

    auto store_s = [&](int st) {
#pragma unroll
        for (int ap = 0; ap < APER; ap++) {
            unsigned* base = SA + st * SASTG + sabase[ap];
            const float v[4] = {aR[ap].x, aR[ap].y, aR[ap].z, aR[ap].w};
#pragma unroll
            for (int i = 0; i < 4; i++)
                base[aslot[ap][i]] = f2tf(v[i]);
        }
#pragma unroll
        for (int bp = 0; bp < BPER; bp++) {
            uint4 u = { f2tf(bR[bp][0].x), f2tf(bR[bp][1].x),
                        f2tf(bR[bp][0].y), f2tf(bR[bp][1].y) };
            *(uint4*)(SB + st * SBSTG + sbbase[bp]) = u;
        }
    };

    auto compute = [&](int st) {
#pragma unroll
        for (int k8 = 0; k8 < 2; k8++) {
            const unsigned* pa = SA + st * SASTG + k8 * (4 * 144);
            const unsigned* pb = SB + st * SBSTG + k8 * (4 * NCP * 2);
            uint4 ua[2];
#pragma unroll
            for (int mt = 0; mt < 2; mt++)
                ua[mt] = *(const uint4*)(pa + (wm * 2 + mt) * 144 + saoff);
            uint2 ub[4];
#pragma unroll
            for (int nt = 0; nt < 4; nt++)
                ub[nt] = *(const uint2*)(pb + tg * (NCP * 2) +
                                         (wn * 32 + nt * 8 + grp) * 2);
#pragma unroll
            for (int mt = 0; mt < 2; mt++) {
                const unsigned a4[4] = {ua[mt].x, ua[mt].z, ua[mt].y, ua[mt].w};
#pragma unroll
                for (int nt = 0; nt < 4; nt++) {
                    const unsigned b2[2] = {ub[nt].x, ub[nt].y};
                    mma8(acc[mt][nt], a4, b2);
                }
            }
        }
    };

    load_g(0);
    store_s(0);
    __syncthreads();

#pragma unroll 1
    for (int kt = 0; kt < NK; kt++) {
        if (kt + 1 < NK) load_g((kt + 1) * BK);
        compute(kt & 1);
        if (kt + 1 < NK) {
            store_s((kt + 1) & 1);
            __syncthreads();
        }
    }

    // epilogue: bias (+ReLU), guarded float2 stores
    const float* bv = bias + e * ND;
    float* Cb = RELU ? g_h1 : g_o2;
#pragma unroll
    for (int mt = 0; mt < 2; mt++) {
        const int lr = wm * 32 + mt * 16 + grp;
#pragma unroll
        for (int half = 0; half < 2; half++) {
            const int r = row0 + lr + half * 8;
            if (r < M) {
                float* crow = Cb + ((size_t)e * TT + r) * ND;
#pragma unroll
                for (int nt = 0; nt < 4; nt++) {
                    const int c = col0 + wn * 32 + nt * 8 + 2 * tg;
                    float v0 = acc[mt][nt][half * 2 + 0] + bv[c];
                    float v1 = acc[mt][nt][half * 2 + 1] + bv[c + 1];
                    if (RELU) { v0 = fmaxf(v0, 0.f); v1 = fmaxf(v1, 0.f); }
                    *(float2*)(crow + c) = make_float2(v0, v1);
                }
            }
        }
    }
}

// ---------------- kernel 4: gated combine (deterministic) ----------------
__global__ void combine_kernel(float* __restrict__ y) {
    const int t  = blockIdx.x;
    const int d4 = threadIdx.x;
    const int   p0 = g_pos[t * 2],     p1 = g_pos[t * 2 + 1];
    const float g0 = g_gv[t * 2],      g1 = g_gv[t * 2 + 1];
    const float4 a = *(const float4*)(g_o2 + (size_t)p0 * DD + d4 * 4);
    const float4 b = *(const float4*)(g_o2 + (size_t)p1 * DD + d4 * 4);
    float4 r;
    r.x = g0 * a.x + g1 * b.x;
    r.y = g0 * a.y + g1 * b.y;
    r.z = g0 * a.z + g1 * b.z;
    r.w = g0 * a.w + g1 * b.w;
    *(float4*)(y + (size_t)t * DD + d4 * 4) = r;
}

// ---------------- launch ----------------
extern "C" void kernel_launch(void* const* d_in, const int* in_sizes, int n_in,
                              void* d_out, int out_size) {
    const float* x  = (const float*)d_in[0];
    const float* wg = (const float*)d_in[1];
    const float* W1 = (const float*)d_in[2];
    const float* b1 = (const float*)d_in[3];
    const float* W2 = (const float*)d_in[4];
    const float* b2 = (const float*)d_in[5];
    float* y = (float*)d_out;

    zero_counts_kernel<<<1, 32>>>();
    gate_kernel<<<TT / 4, 128>>>(x, wg);
    // GEMM1: (gathered tokens) x W1 -> relu(.+b1) into g_h1.  64x128 tiles.
    moe_gemm_kernel<HH, DD, 128, 256, true,  true ><<<dim3(HH / 128, TT / 64, EE), 256>>>(x, W1, b1);
    // GEMM2: g_h1 x W2 -> (.+b2) into g_o2.  64x64 tiles for SM coverage.
    moe_gemm_kernel<DD, HH, 64, 128, false, false><<<dim3(DD / 64, TT / 64, EE), 128>>>(nullptr, W2, b2);
    combine_kernel<<<TT, 64>>>(y);
}